// round 1
// baseline (speedup 1.0000x reference)
#include <cuda_runtime.h>
#include <cuda_bf16.h>
#include <math_constants.h>

// Problem constants
#define B_  8
#define L_  1024
#define D_  256
#define H_  8
#define HD_ 2048            // H_*D_
#define F_  1024            // N_MLP*D_ = 4*256
#define ROWS_ (B_*L_)       // 8192
#define EPS_ 1e-5f

// --------------------------- scratch (device globals, no allocs) ------------
__device__ float g_Q[(size_t)ROWS_ * HD_];   // 64MB  [b,l, h*256+e]
__device__ float g_K[(size_t)ROWS_ * HD_];   // 64MB
__device__ float g_V[(size_t)ROWS_ * HD_];   // 64MB
__device__ float g_S[(size_t)B_ * H_ * L_ * L_]; // 256MB scores/probs
__device__ float g_O[(size_t)ROWS_ * HD_];   // 64MB attention out [b,l,h*256+e]
__device__ float g_R1[(size_t)ROWS_ * D_];   // attn + x
__device__ float g_Z1[(size_t)ROWS_ * D_];   // LN1 out
__device__ float g_Hb[(size_t)ROWS_ * F_];   // FFN hidden (32MB)
__device__ float g_F[(size_t)ROWS_ * D_];    // ffn out + z1

// --------------------------- generic SGEMM: C = alpha*A*B^T (+bias +resid, relu)
// A: [M,K] row-major (lda), B: [N,K] row-major (ldb), C: [M,N] (ldc)
// tiles 64x64x64, 256 threads (16x16), 4x4 per thread
__global__ void sgemm_abt(const float* __restrict__ A, const float* __restrict__ B,
                          float* __restrict__ C,
                          int K, int lda, int ldb, int ldc, float alpha,
                          const float* __restrict__ bias,
                          const float* __restrict__ resid, int ldres, int relu)
{
    __shared__ float As[64][68];   // As[k][m]
    __shared__ float Bs[64][68];   // Bs[k][n]
    const int tx = threadIdx.x, ty = threadIdx.y;
    const int tid = ty * 16 + tx;
    const int row0 = blockIdx.y * 64, col0 = blockIdx.x * 64;

    float acc[4][4] = {};

    for (int k0 = 0; k0 < K; k0 += 64) {
#pragma unroll
        for (int t = tid; t < 64 * 64; t += 256) {
            int r = t >> 6, c = t & 63;
            As[c][r] = A[(size_t)(row0 + r) * lda + k0 + c];
            Bs[c][r] = B[(size_t)(col0 + r) * ldb + k0 + c];
        }
        __syncthreads();
#pragma unroll
        for (int k = 0; k < 64; k++) {
            const float4 a4 = *(const float4*)&As[k][ty * 4];
            const float4 b4 = *(const float4*)&Bs[k][tx * 4];
            const float av[4] = {a4.x, a4.y, a4.z, a4.w};
            const float bv[4] = {b4.x, b4.y, b4.z, b4.w};
#pragma unroll
            for (int i = 0; i < 4; i++)
#pragma unroll
                for (int j = 0; j < 4; j++)
                    acc[i][j] += av[i] * bv[j];
        }
        __syncthreads();
    }

#pragma unroll
    for (int i = 0; i < 4; i++) {
        const int r = row0 + ty * 4 + i;
#pragma unroll
        for (int j = 0; j < 4; j++) {
            const int c = col0 + tx * 4 + j;
            float v = acc[i][j] * alpha;
            if (bias)  v += bias[c];
            if (resid) v += resid[(size_t)r * ldres + c];
            if (relu)  v = fmaxf(v, 0.f);
            C[(size_t)r * ldc + c] = v;
        }
    }
}

// --------------------------- batched QK^T: S[z] = (1/16) Q[z] K[z]^T ---------
// Q/K stored [b, l, h*256+e]; z = b*8+h; M=N=1024, K=256
__global__ void scores_kernel(const float* __restrict__ Qb,
                              const float* __restrict__ Kb,
                              float* __restrict__ S)
{
    __shared__ float As[64][68];
    __shared__ float Bs[64][68];
    const int z = blockIdx.z, b = z >> 3, h = z & 7;
    const float* A = Qb + (size_t)b * L_ * HD_ + h * D_;  // lda = HD_
    const float* Bm = Kb + (size_t)b * L_ * HD_ + h * D_;
    float* C = S + (size_t)z * L_ * L_;

    const int tx = threadIdx.x, ty = threadIdx.y;
    const int tid = ty * 16 + tx;
    const int row0 = blockIdx.y * 64, col0 = blockIdx.x * 64;
    float acc[4][4] = {};

    for (int k0 = 0; k0 < D_; k0 += 64) {
#pragma unroll
        for (int t = tid; t < 64 * 64; t += 256) {
            int r = t >> 6, c = t & 63;
            As[c][r] = A[(size_t)(row0 + r) * HD_ + k0 + c];
            Bs[c][r] = Bm[(size_t)(col0 + r) * HD_ + k0 + c];
        }
        __syncthreads();
#pragma unroll
        for (int k = 0; k < 64; k++) {
            const float4 a4 = *(const float4*)&As[k][ty * 4];
            const float4 b4 = *(const float4*)&Bs[k][tx * 4];
            const float av[4] = {a4.x, a4.y, a4.z, a4.w};
            const float bv[4] = {b4.x, b4.y, b4.z, b4.w};
#pragma unroll
            for (int i = 0; i < 4; i++)
#pragma unroll
                for (int j = 0; j < 4; j++)
                    acc[i][j] += av[i] * bv[j];
        }
        __syncthreads();
    }
#pragma unroll
    for (int i = 0; i < 4; i++)
#pragma unroll
        for (int j = 0; j < 4; j++)
            C[(size_t)(row0 + ty * 4 + i) * L_ + col0 + tx * 4 + j] =
                acc[i][j] * 0.0625f;   // 1/sqrt(256)
}

// --------------------------- softmax over last dim (1024), in-place ---------
__global__ void softmax_kernel(float* __restrict__ S)
{
    __shared__ float red[8];
    const size_t row = blockIdx.x;
    float* p = S + row * (size_t)L_;
    const int t = threadIdx.x;

    float4 v = reinterpret_cast<float4*>(p)[t];
    float m = fmaxf(fmaxf(v.x, v.y), fmaxf(v.z, v.w));
#pragma unroll
    for (int o = 16; o; o >>= 1) m = fmaxf(m, __shfl_xor_sync(~0u, m, o));
    if ((t & 31) == 0) red[t >> 5] = m;
    __syncthreads();
    float mm = red[0];
#pragma unroll
    for (int i = 1; i < 8; i++) mm = fmaxf(mm, red[i]);
    __syncthreads();

    v.x = expf(v.x - mm); v.y = expf(v.y - mm);
    v.z = expf(v.z - mm); v.w = expf(v.w - mm);
    float s = v.x + v.y + v.z + v.w;
#pragma unroll
    for (int o = 16; o; o >>= 1) s += __shfl_xor_sync(~0u, s, o);
    if ((t & 31) == 0) red[t >> 5] = s;
    __syncthreads();
    float ss = 0.f;
#pragma unroll
    for (int i = 0; i < 8; i++) ss += red[i];
    const float inv = 1.f / ss;
    v.x *= inv; v.y *= inv; v.z *= inv; v.w *= inv;
    reinterpret_cast<float4*>(p)[t] = v;
}

// --------------------------- batched PV: O[b,l,h*256+e] = P[z] @ V[z] --------
// P: [1024,1024] per z ; V[z][j][e] = g_V[(b*1024+j)*2048 + h*256 + e]
__global__ void av_kernel(const float* __restrict__ P,
                          const float* __restrict__ Vb,
                          float* __restrict__ O)
{
    __shared__ float As[64][68];  // As[k][m]  (k = j dim)
    __shared__ float Bs[64][68];  // Bs[k][n]
    const int z = blockIdx.z, b = z >> 3, h = z & 7;
    const float* A = P + (size_t)z * L_ * L_;
    const float* Bm = Vb + (size_t)b * L_ * HD_ + h * D_;

    const int tx = threadIdx.x, ty = threadIdx.y;
    const int tid = ty * 16 + tx;
    const int row0 = blockIdx.y * 64, col0 = blockIdx.x * 64;
    float acc[4][4] = {};

    for (int k0 = 0; k0 < L_; k0 += 64) {
#pragma unroll
        for (int t = tid; t < 64 * 64; t += 256) {
            int r = t >> 6, c = t & 63;
            As[c][r] = A[(size_t)(row0 + r) * L_ + k0 + c];   // transposed store
            Bs[r][c] = Bm[(size_t)(k0 + r) * HD_ + col0 + c]; // direct store
        }
        __syncthreads();
#pragma unroll
        for (int k = 0; k < 64; k++) {
            const float4 a4 = *(const float4*)&As[k][ty * 4];
            const float4 b4 = *(const float4*)&Bs[k][tx * 4];
            const float av[4] = {a4.x, a4.y, a4.z, a4.w};
            const float bv[4] = {b4.x, b4.y, b4.z, b4.w};
#pragma unroll
            for (int i = 0; i < 4; i++)
#pragma unroll
                for (int j = 0; j < 4; j++)
                    acc[i][j] += av[i] * bv[j];
        }
        __syncthreads();
    }
#pragma unroll
    for (int i = 0; i < 4; i++) {
        const size_t r = (size_t)b * L_ + row0 + ty * 4 + i;
#pragma unroll
        for (int j = 0; j < 4; j++)
            O[r * HD_ + h * D_ + col0 + tx * 4 + j] = acc[i][j];
    }
}

// --------------------------- layernorm over d=256 ---------------------------
__global__ void ln_kernel(const float* __restrict__ in, float* __restrict__ out,
                          const float* __restrict__ g, const float* __restrict__ be)
{
    __shared__ float r1[8], r2[8];
    const int row = blockIdx.x, t = threadIdx.x;
    const float v = in[(size_t)row * D_ + t];
    float s = v, q = v * v;
#pragma unroll
    for (int o = 16; o; o >>= 1) {
        s += __shfl_xor_sync(~0u, s, o);
        q += __shfl_xor_sync(~0u, q, o);
    }
    if ((t & 31) == 0) { r1[t >> 5] = s; r2[t >> 5] = q; }
    __syncthreads();
    float S = 0.f, Q = 0.f;
#pragma unroll
    for (int i = 0; i < 8; i++) { S += r1[i]; Q += r2[i]; }
    const float mean = S * (1.f / D_);
    const float var = Q * (1.f / D_) - mean * mean;
    out[(size_t)row * D_ + t] = (v - mean) * rsqrtf(var + EPS_) * g[t] + be[t];
}

// --------------------------- launch -----------------------------------------
extern "C" void kernel_launch(void* const* d_in, const int* in_sizes, int n_in,
                              void* d_out, int out_size)
{
    const float* x   = (const float*)d_in[0];
    const float* Wq  = (const float*)d_in[1];
    const float* Wk  = (const float*)d_in[2];
    const float* Wv  = (const float*)d_in[3];
    const float* Wu  = (const float*)d_in[4];
    const float* bu  = (const float*)d_in[5];
    const float* W1  = (const float*)d_in[6];
    const float* b1  = (const float*)d_in[7];
    const float* W2  = (const float*)d_in[8];
    const float* b2  = (const float*)d_in[9];
    const float* g1  = (const float*)d_in[10];
    const float* be1 = (const float*)d_in[11];
    const float* g2  = (const float*)d_in[12];
    const float* be2 = (const float*)d_in[13];
    float* out = (float*)d_out;

    float *Qb, *Kb, *Vb, *S, *O, *R1, *Z1, *Hb, *F;
    cudaGetSymbolAddress((void**)&Qb, g_Q);
    cudaGetSymbolAddress((void**)&Kb, g_K);
    cudaGetSymbolAddress((void**)&Vb, g_V);
    cudaGetSymbolAddress((void**)&S,  g_S);
    cudaGetSymbolAddress((void**)&O,  g_O);
    cudaGetSymbolAddress((void**)&R1, g_R1);
    cudaGetSymbolAddress((void**)&Z1, g_Z1);
    cudaGetSymbolAddress((void**)&Hb, g_Hb);
    cudaGetSymbolAddress((void**)&F,  g_F);

    const dim3 thr(16, 16);

    // QKV projections: [8192,256] @ [2048,256]^T -> [8192,2048]
    sgemm_abt<<<dim3(HD_ / 64, ROWS_ / 64, 1), thr>>>(x, Wq, Qb, D_, D_, D_, HD_, 1.f, nullptr, nullptr, 0, 0);
    sgemm_abt<<<dim3(HD_ / 64, ROWS_ / 64, 1), thr>>>(x, Wk, Kb, D_, D_, D_, HD_, 1.f, nullptr, nullptr, 0, 0);
    sgemm_abt<<<dim3(HD_ / 64, ROWS_ / 64, 1), thr>>>(x, Wv, Vb, D_, D_, D_, HD_, 1.f, nullptr, nullptr, 0, 0);

    // scores + softmax + PV
    scores_kernel<<<dim3(L_ / 64, L_ / 64, B_ * H_), thr>>>(Qb, Kb, S);
    softmax_kernel<<<B_ * H_ * L_, 256>>>(S);
    av_kernel<<<dim3(D_ / 64, L_ / 64, B_ * H_), thr>>>(S, Vb, O);

    // output projection + bias + residual(x)
    sgemm_abt<<<dim3(D_ / 64, ROWS_ / 64, 1), thr>>>(O, Wu, R1, HD_, HD_, HD_, D_, 1.f, bu, x, D_, 0);
    ln_kernel<<<ROWS_, 256>>>(R1, Z1, g1, be1);

    // FFN
    sgemm_abt<<<dim3(F_ / 64, ROWS_ / 64, 1), thr>>>(Z1, W1, Hb, D_, D_, D_, F_, 1.f, b1, nullptr, 0, 1);
    sgemm_abt<<<dim3(D_ / 64, ROWS_ / 64, 1), thr>>>(Hb, W2, F, F_, F_, F_, D_, 1.f, b2, Z1, D_, 0);
    ln_kernel<<<ROWS_, 256>>>(F, out, g2, be2);
}

// round 2
// speedup vs baseline: 6.2820x; 6.2820x over previous
#include <cuda_runtime.h>
#include <cstdint>

#define B_  8
#define L_  1024
#define D_  256
#define H_  8
#define HD_ 2048            // H_*D_
#define F_  1024            // N_MLP*D_
#define ROWS_ (B_*L_)       // 8192
#define EPS_ 1e-5f

// --------------------------- scratch (device globals, no allocs) ------------
__device__ float g_Q[(size_t)ROWS_ * HD_];
__device__ float g_K[(size_t)ROWS_ * HD_];
__device__ float g_V[(size_t)ROWS_ * HD_];
__device__ float g_S[(size_t)B_ * H_ * L_ * L_];
__device__ float g_O[(size_t)ROWS_ * HD_];
__device__ float g_R1[(size_t)ROWS_ * D_];
__device__ float g_Z1[(size_t)ROWS_ * D_];
__device__ float g_Hb[(size_t)ROWS_ * F_];
__device__ float g_F[(size_t)ROWS_ * D_];

// --------------------------- tf32 helpers -----------------------------------
__device__ __forceinline__ uint32_t f2tf(float f) {
    uint32_t u;
    asm("cvt.rna.tf32.f32 %0, %1;" : "=r"(u) : "f"(f));
    return u;
}

__device__ __forceinline__ void mma8(float* c, const uint32_t* a, const uint32_t* b) {
    asm volatile(
        "mma.sync.aligned.m16n8k8.row.col.f32.tf32.tf32.f32 "
        "{%0,%1,%2,%3}, {%4,%5,%6,%7}, {%8,%9}, {%0,%1,%2,%3};"
        : "+f"(c[0]), "+f"(c[1]), "+f"(c[2]), "+f"(c[3])
        : "r"(a[0]), "r"(a[1]), "r"(a[2]), "r"(a[3]), "r"(b[0]), "r"(b[1]));
}

// ============================================================================
// Generic tf32 GEMM: C = alpha * A @ B^T (+bias +resid, optional relu)
// A: [M,K] row-major (lda), B: [N,K] row-major (ldb), C: [M,N] (ldc)
// Block: 128x128x32, 256 threads, 8 warps (4M x 2N), warp tile 32x64.
// Batch via blockIdx.z: off = (z>>3)*s1 + (z&7)*s2 for A/B/C.
// Smem layouts: [row][k] with pitch 36 floats -> conflict-free frag LDS.
// ============================================================================
__global__ __launch_bounds__(256)
void mm_tf32(const float* __restrict__ A, const float* __restrict__ Bm,
             float* __restrict__ C, int K, int lda, int ldb, int ldc,
             long long sA1, long long sA2, long long sB1, long long sB2,
             long long sC1, long long sC2,
             float alpha, const float* __restrict__ bias,
             const float* __restrict__ resid, int ldres, int relu)
{
    __shared__ uint32_t As[128 * 36];
    __shared__ uint32_t Bs[128 * 36];

    const int z = blockIdx.z;
    A  += (size_t)(z >> 3) * sA1 + (size_t)(z & 7) * sA2;
    Bm += (size_t)(z >> 3) * sB1 + (size_t)(z & 7) * sB2;
    C  += (size_t)(z >> 3) * sC1 + (size_t)(z & 7) * sC2;

    const int tid  = threadIdx.x;
    const int row0 = blockIdx.y * 128, col0 = blockIdx.x * 128;
    const int warp = tid >> 5, lane = tid & 31;
    const int wm = warp & 3, wn = warp >> 2;       // 4 x 2 warp grid
    const int g = lane >> 2, tg = lane & 3;

    float acc[2][8][4] = {};
    float4 va[4], vb[4];

    // prefetch first k-tile
#pragma unroll
    for (int i = 0; i < 4; i++) {
        const int s = tid + i * 256, r = s >> 3, kq = s & 7;
        va[i] = *(const float4*)&A[(size_t)(row0 + r) * lda + kq * 4];
        vb[i] = *(const float4*)&Bm[(size_t)(col0 + r) * ldb + kq * 4];
    }

    for (int k0 = 0; k0 < K; k0 += 32) {
        // stage current tile (tf32-converted, STS.128)
#pragma unroll
        for (int i = 0; i < 4; i++) {
            const int s = tid + i * 256, r = s >> 3, kq = s & 7;
            uint4 ua = make_uint4(f2tf(va[i].x), f2tf(va[i].y), f2tf(va[i].z), f2tf(va[i].w));
            uint4 ub = make_uint4(f2tf(vb[i].x), f2tf(vb[i].y), f2tf(vb[i].z), f2tf(vb[i].w));
            *(uint4*)&As[r * 36 + kq * 4] = ua;
            *(uint4*)&Bs[r * 36 + kq * 4] = ub;
        }
        __syncthreads();

        // prefetch next k-tile into registers
        if (k0 + 32 < K) {
#pragma unroll
            for (int i = 0; i < 4; i++) {
                const int s = tid + i * 256, r = s >> 3, kq = s & 7;
                va[i] = *(const float4*)&A[(size_t)(row0 + r) * lda + k0 + 32 + kq * 4];
                vb[i] = *(const float4*)&Bm[(size_t)(col0 + r) * ldb + k0 + 32 + kq * 4];
            }
        }

#pragma unroll
        for (int ks = 0; ks < 32; ks += 8) {
            uint32_t a[2][4], b[8][2];
#pragma unroll
            for (int mf = 0; mf < 2; mf++) {
                const int m0 = wm * 32 + mf * 16;
                a[mf][0] = As[(m0 + g) * 36 + ks + tg];
                a[mf][1] = As[(m0 + 8 + g) * 36 + ks + tg];
                a[mf][2] = As[(m0 + g) * 36 + ks + 4 + tg];
                a[mf][3] = As[(m0 + 8 + g) * 36 + ks + 4 + tg];
            }
#pragma unroll
            for (int nf = 0; nf < 8; nf++) {
                const int n0 = wn * 64 + nf * 8;
                b[nf][0] = Bs[(n0 + g) * 36 + ks + tg];
                b[nf][1] = Bs[(n0 + g) * 36 + ks + 4 + tg];
            }
#pragma unroll
            for (int mf = 0; mf < 2; mf++)
#pragma unroll
                for (int nf = 0; nf < 8; nf++)
                    mma8(acc[mf][nf], a[mf], b[nf]);
        }
        __syncthreads();
    }

    // epilogue
#pragma unroll
    for (int mf = 0; mf < 2; mf++) {
#pragma unroll
        for (int nf = 0; nf < 8; nf++) {
            const int r = row0 + wm * 32 + mf * 16 + g;
            const int c = col0 + wn * 64 + nf * 8 + 2 * tg;
#pragma unroll
            for (int q = 0; q < 4; q++) {
                const int rr = r + (q >> 1) * 8;
                const int cc = c + (q & 1);
                float v = acc[mf][nf][q] * alpha;
                if (bias)  v += bias[cc];
                if (resid) v += resid[(size_t)rr * ldres + cc];
                if (relu)  v = fmaxf(v, 0.f);
                C[(size_t)rr * ldc + cc] = v;
            }
        }
    }
}

// ============================================================================
// PV: O[b, l, h*256+e] = P[z] @ V[z]   (z = b*8+h), tf32
// A = P [1024,1024] row-major; V slice [j][e] needs B(k=j, n=e):
// stage Vs as [k][n] with pitch 136 (8 mod 32) -> conflict-free frag LDS.
// ============================================================================
__global__ __launch_bounds__(256)
void av_tf32(const float* __restrict__ P, const float* __restrict__ Vb,
             float* __restrict__ O)
{
    __shared__ uint32_t As[128 * 36];
    __shared__ uint32_t Vs[32 * 136];

    const int z = blockIdx.z, b = z >> 3, h = z & 7;
    const float* A = P + (size_t)z * L_ * L_;
    const float* V = Vb + (size_t)b * L_ * HD_ + h * D_;

    const int tid  = threadIdx.x;
    const int row0 = blockIdx.y * 128, col0 = blockIdx.x * 128;
    const int warp = tid >> 5, lane = tid & 31;
    const int wm = warp & 3, wn = warp >> 2;
    const int g = lane >> 2, tg = lane & 3;

    float acc[2][8][4] = {};
    float4 va[4], vv[4];

#pragma unroll
    for (int i = 0; i < 4; i++) {
        { const int s = tid + i * 256, r = s >> 3, kq = s & 7;
          va[i] = *(const float4*)&A[(size_t)(row0 + r) * L_ + kq * 4]; }
        { const int s = tid + i * 256, j = s >> 5, eg = s & 31;
          vv[i] = *(const float4*)&V[(size_t)j * HD_ + col0 + eg * 4]; }
    }

    for (int k0 = 0; k0 < L_; k0 += 32) {
#pragma unroll
        for (int i = 0; i < 4; i++) {
            { const int s = tid + i * 256, r = s >> 3, kq = s & 7;
              uint4 u = make_uint4(f2tf(va[i].x), f2tf(va[i].y), f2tf(va[i].z), f2tf(va[i].w));
              *(uint4*)&As[r * 36 + kq * 4] = u; }
            { const int s = tid + i * 256, j = s >> 5, eg = s & 31;
              uint4 u = make_uint4(f2tf(vv[i].x), f2tf(vv[i].y), f2tf(vv[i].z), f2tf(vv[i].w));
              *(uint4*)&Vs[j * 136 + eg * 4] = u; }
        }
        __syncthreads();

        if (k0 + 32 < L_) {
#pragma unroll
            for (int i = 0; i < 4; i++) {
                { const int s = tid + i * 256, r = s >> 3, kq = s & 7;
                  va[i] = *(const float4*)&A[(size_t)(row0 + r) * L_ + k0 + 32 + kq * 4]; }
                { const int s = tid + i * 256, j = s >> 5, eg = s & 31;
                  vv[i] = *(const float4*)&V[(size_t)(k0 + 32 + j) * HD_ + col0 + eg * 4]; }
            }
        }

#pragma unroll
        for (int ks = 0; ks < 32; ks += 8) {
            uint32_t a[2][4], bfr[8][2];
#pragma unroll
            for (int mf = 0; mf < 2; mf++) {
                const int m0 = wm * 32 + mf * 16;
                a[mf][0] = As[(m0 + g) * 36 + ks + tg];
                a[mf][1] = As[(m0 + 8 + g) * 36 + ks + tg];
                a[mf][2] = As[(m0 + g) * 36 + ks + 4 + tg];
                a[mf][3] = As[(m0 + 8 + g) * 36 + ks + 4 + tg];
            }
#pragma unroll
            for (int nf = 0; nf < 8; nf++) {
                const int n0 = wn * 64 + nf * 8;
                bfr[nf][0] = Vs[(ks + tg) * 136 + n0 + g];
                bfr[nf][1] = Vs[(ks + 4 + tg) * 136 + n0 + g];
            }
#pragma unroll
            for (int mf = 0; mf < 2; mf++)
#pragma unroll
                for (int nf = 0; nf < 8; nf++)
                    mma8(acc[mf][nf], a[mf], bfr[nf]);
        }
        __syncthreads();
    }

#pragma unroll
    for (int mf = 0; mf < 2; mf++) {
#pragma unroll
        for (int nf = 0; nf < 8; nf++) {
            const int r = row0 + wm * 32 + mf * 16 + g;
            const int c = col0 + wn * 64 + nf * 8 + 2 * tg;
#pragma unroll
            for (int q = 0; q < 4; q++) {
                const int rr = r + (q >> 1) * 8;
                const int cc = c + (q & 1);
                O[(size_t)(b * L_ + rr) * HD_ + h * D_ + cc] = acc[mf][nf][q];
            }
        }
    }
}

// --------------------------- softmax over last dim (1024), in-place ---------
__global__ void softmax_kernel(float* __restrict__ S)
{
    __shared__ float red[8];
    const size_t row = blockIdx.x;
    float* p = S + row * (size_t)L_;
    const int t = threadIdx.x;

    float4 v = reinterpret_cast<float4*>(p)[t];
    float m = fmaxf(fmaxf(v.x, v.y), fmaxf(v.z, v.w));
#pragma unroll
    for (int o = 16; o; o >>= 1) m = fmaxf(m, __shfl_xor_sync(~0u, m, o));
    if ((t & 31) == 0) red[t >> 5] = m;
    __syncthreads();
    float mm = red[0];
#pragma unroll
    for (int i = 1; i < 8; i++) mm = fmaxf(mm, red[i]);
    __syncthreads();

    v.x = expf(v.x - mm); v.y = expf(v.y - mm);
    v.z = expf(v.z - mm); v.w = expf(v.w - mm);
    float s = v.x + v.y + v.z + v.w;
#pragma unroll
    for (int o = 16; o; o >>= 1) s += __shfl_xor_sync(~0u, s, o);
    if ((t & 31) == 0) red[t >> 5] = s;
    __syncthreads();
    float ss = 0.f;
#pragma unroll
    for (int i = 0; i < 8; i++) ss += red[i];
    const float inv = 1.f / ss;
    v.x *= inv; v.y *= inv; v.z *= inv; v.w *= inv;
    reinterpret_cast<float4*>(p)[t] = v;
}

// --------------------------- layernorm over d=256 ---------------------------
__global__ void ln_kernel(const float* __restrict__ in, float* __restrict__ out,
                          const float* __restrict__ g, const float* __restrict__ be)
{
    __shared__ float r1[8], r2[8];
    const int row = blockIdx.x, t = threadIdx.x;
    const float v = in[(size_t)row * D_ + t];
    float s = v, q = v * v;
#pragma unroll
    for (int o = 16; o; o >>= 1) {
        s += __shfl_xor_sync(~0u, s, o);
        q += __shfl_xor_sync(~0u, q, o);
    }
    if ((t & 31) == 0) { r1[t >> 5] = s; r2[t >> 5] = q; }
    __syncthreads();
    float S = 0.f, Q = 0.f;
#pragma unroll
    for (int i = 0; i < 8; i++) { S += r1[i]; Q += r2[i]; }
    const float mean = S * (1.f / D_);
    const float var = Q * (1.f / D_) - mean * mean;
    out[(size_t)row * D_ + t] = (v - mean) * rsqrtf(var + EPS_) * g[t] + be[t];
}

// --------------------------- launch -----------------------------------------
extern "C" void kernel_launch(void* const* d_in, const int* in_sizes, int n_in,
                              void* d_out, int out_size)
{
    const float* x   = (const float*)d_in[0];
    const float* Wq  = (const float*)d_in[1];
    const float* Wk  = (const float*)d_in[2];
    const float* Wv  = (const float*)d_in[3];
    const float* Wu  = (const float*)d_in[4];
    const float* bu  = (const float*)d_in[5];
    const float* W1  = (const float*)d_in[6];
    const float* b1  = (const float*)d_in[7];
    const float* W2  = (const float*)d_in[8];
    const float* b2  = (const float*)d_in[9];
    const float* g1  = (const float*)d_in[10];
    const float* be1 = (const float*)d_in[11];
    const float* g2  = (const float*)d_in[12];
    const float* be2 = (const float*)d_in[13];
    float* out = (float*)d_out;

    float *Qb, *Kb, *Vb, *S, *O, *R1, *Z1, *Hb, *F;
    cudaGetSymbolAddress((void**)&Qb, g_Q);
    cudaGetSymbolAddress((void**)&Kb, g_K);
    cudaGetSymbolAddress((void**)&Vb, g_V);
    cudaGetSymbolAddress((void**)&S,  g_S);
    cudaGetSymbolAddress((void**)&O,  g_O);
    cudaGetSymbolAddress((void**)&R1, g_R1);
    cudaGetSymbolAddress((void**)&Z1, g_Z1);
    cudaGetSymbolAddress((void**)&Hb, g_Hb);
    cudaGetSymbolAddress((void**)&F,  g_F);

    const long long LL2 = (long long)L_ * L_;

    // QKV projections: [8192,256] @ [2048,256]^T
    mm_tf32<<<dim3(HD_ / 128, ROWS_ / 128, 1), 256>>>(x, Wq, Qb, D_, D_, D_, HD_,
        0, 0, 0, 0, 0, 0, 1.f, nullptr, nullptr, 0, 0);
    mm_tf32<<<dim3(HD_ / 128, ROWS_ / 128, 1), 256>>>(x, Wk, Kb, D_, D_, D_, HD_,
        0, 0, 0, 0, 0, 0, 1.f, nullptr, nullptr, 0, 0);
    mm_tf32<<<dim3(HD_ / 128, ROWS_ / 128, 1), 256>>>(x, Wv, Vb, D_, D_, D_, HD_,
        0, 0, 0, 0, 0, 0, 1.f, nullptr, nullptr, 0, 0);

    // scores: per (b,h): Q[1024,256] @ K^T / 16
    mm_tf32<<<dim3(L_ / 128, L_ / 128, B_ * H_), 256>>>(Qb, Kb, S, D_, HD_, HD_, L_,
        (long long)L_ * HD_, D_, (long long)L_ * HD_, D_, 8 * LL2, LL2,
        0.0625f, nullptr, nullptr, 0, 0);

    softmax_kernel<<<B_ * H_ * L_, 256>>>(S);

    // PV
    av_tf32<<<dim3(D_ / 128, L_ / 128, B_ * H_), 256>>>(S, Vb, O);

    // output projection + bias + residual(x)
    mm_tf32<<<dim3(D_ / 128, ROWS_ / 128, 1), 256>>>(O, Wu, R1, HD_, HD_, HD_, D_,
        0, 0, 0, 0, 0, 0, 1.f, bu, x, D_, 0);
    ln_kernel<<<ROWS_, 256>>>(R1, Z1, g1, be1);

    // FFN
    mm_tf32<<<dim3(F_ / 128, ROWS_ / 128, 1), 256>>>(Z1, W1, Hb, D_, D_, D_, F_,
        0, 0, 0, 0, 0, 0, 1.f, b1, nullptr, 0, 1);
    mm_tf32<<<dim3(D_ / 128, ROWS_ / 128, 1), 256>>>(Hb, W2, F, F_, F_, F_, D_,
        0, 0, 0, 0, 0, 0, 1.f, b2, Z1, D_, 0);
    ln_kernel<<<ROWS_, 256>>>(F, out, g2, be2);
}

// round 3
// speedup vs baseline: 7.2725x; 1.1577x over previous
#include <cuda_runtime.h>
#include <cstdint>

#define B_  8
#define L_  1024
#define D_  256
#define H_  8
#define HD_ 2048
#define F_  1024
#define ROWS_ (B_*L_)
#define EPS_ 1e-5f

// --------------------------- scratch (device globals) ------------------------
__device__ float g_Q[(size_t)ROWS_ * HD_];
__device__ float g_K[(size_t)ROWS_ * HD_];
__device__ float g_V[(size_t)ROWS_ * HD_];
__device__ float g_S[(size_t)B_ * H_ * L_ * L_];
__device__ float g_O[(size_t)ROWS_ * HD_];
__device__ float g_R1[(size_t)ROWS_ * D_];
__device__ float g_Z1[(size_t)ROWS_ * D_];   // exact LN1 out (residual)
__device__ float g_Z1r[(size_t)ROWS_ * D_];  // tf32-rounded LN1 out (GEMM A)
__device__ float g_Hb[(size_t)ROWS_ * F_];
__device__ float g_F[(size_t)ROWS_ * D_];
// tf32-rounded copies of inputs
__device__ float g_xr[(size_t)ROWS_ * D_];
__device__ float g_Wqr[(size_t)HD_ * D_];
__device__ float g_Wkr[(size_t)HD_ * D_];
__device__ float g_Wvr[(size_t)HD_ * D_];
__device__ float g_Wur[(size_t)D_ * HD_];
__device__ float g_W1r[(size_t)F_ * D_];
__device__ float g_W2r[(size_t)D_ * F_];

// --------------------------- helpers ----------------------------------------
__device__ __forceinline__ uint32_t f2tf(float f) {
    uint32_t u;
    asm("cvt.rna.tf32.f32 %0, %1;" : "=r"(u) : "f"(f));
    return u;
}
__device__ __forceinline__ float f2tf_f(float f) {
    return __uint_as_float(f2tf(f));
}
__device__ __forceinline__ void mma8(float* c, const uint32_t* a, const uint32_t* b) {
    asm volatile(
        "mma.sync.aligned.m16n8k8.row.col.f32.tf32.tf32.f32 "
        "{%0,%1,%2,%3}, {%4,%5,%6,%7}, {%8,%9}, {%0,%1,%2,%3};"
        : "+f"(c[0]), "+f"(c[1]), "+f"(c[2]), "+f"(c[3])
        : "r"(a[0]), "r"(a[1]), "r"(a[2]), "r"(a[3]), "r"(b[0]), "r"(b[1]));
}
__device__ __forceinline__ void cp16(uint32_t saddr, const void* gptr) {
    asm volatile("cp.async.cg.shared.global [%0], [%1], 16;" :: "r"(saddr), "l"(gptr));
}
__device__ __forceinline__ void cp_commit() { asm volatile("cp.async.commit_group;"); }
__device__ __forceinline__ void cp_wait1()  { asm volatile("cp.async.wait_group 1;"); }
__device__ __forceinline__ void cp_wait0()  { asm volatile("cp.async.wait_group 0;"); }

// --------------------------- tf32 rounding pass ------------------------------
__global__ void cvt_tf32_kernel(const float4* __restrict__ in, float4* __restrict__ out, int n4)
{
    for (int i = blockIdx.x * blockDim.x + threadIdx.x; i < n4; i += gridDim.x * blockDim.x) {
        float4 v = in[i];
        v.x = f2tf_f(v.x); v.y = f2tf_f(v.y); v.z = f2tf_f(v.z); v.w = f2tf_f(v.w);
        out[i] = v;
    }
}

// ============================================================================
// tf32 GEMM: C = alpha * A @ B^T (+bias +resid, relu, tf32-round output)
// A: [M,K] (lda), B: [N,K] (ldb), C: [M,N] (ldc). A,B pre-rounded to tf32.
// Block tile: 128 x (NF*16) x 32, 256 threads, 8 warps (4M x 2N),
// warp tile 32 x (NF*8). 2-stage cp.async pipeline, 2 CTAs/SM.
// ============================================================================
template<int NF>
__global__ __launch_bounds__(256, 2)
void mm_tf32(const float* __restrict__ A, const float* __restrict__ Bm,
             float* __restrict__ C, int K, int lda, int ldb, int ldc,
             long long sA1, long long sA2, long long sB1, long long sB2,
             long long sC1, long long sC2,
             float alpha, const float* __restrict__ bias,
             const float* __restrict__ resid, int ldres, int relu, int round_out)
{
    constexpr int BN   = NF * 16;
    constexpr int ASTG = 128 * 36;         // uint32 per stage (A part)
    constexpr int BSTG = BN * 36;
    constexpr int STG  = ASTG + BSTG;

    extern __shared__ uint32_t sm[];

    const int z = blockIdx.z;
    A  += (size_t)(z >> 3) * sA1 + (size_t)(z & 7) * sA2;
    Bm += (size_t)(z >> 3) * sB1 + (size_t)(z & 7) * sB2;
    C  += (size_t)(z >> 3) * sC1 + (size_t)(z & 7) * sC2;

    const int tid  = threadIdx.x;
    const int row0 = blockIdx.y * 128, col0 = blockIdx.x * BN;
    const int warp = tid >> 5, lane = tid & 31;
    const int wm = warp & 3, wn = warp >> 2;
    const int g = lane >> 2, tg = lane & 3;

    const uint32_t smb = (uint32_t)__cvta_generic_to_shared(sm);

    float acc[2][NF][4] = {};

    auto stage = [&](int st, int k0) {
        const uint32_t baseA = smb + (uint32_t)(st * STG) * 4u;
        const uint32_t baseB = baseA + (uint32_t)ASTG * 4u;
#pragma unroll
        for (int i = 0; i < 4; i++) {
            const int s = tid + i * 256, r = s >> 3, kq = s & 7;
            cp16(baseA + (uint32_t)(r * 36 + kq * 4) * 4u,
                 A + (size_t)(row0 + r) * lda + k0 + kq * 4);
        }
#pragma unroll
        for (int i = 0; i < NF / 2; i++) {
            const int s = tid + i * 256, r = s >> 3, kq = s & 7;
            cp16(baseB + (uint32_t)(r * 36 + kq * 4) * 4u,
                 Bm + (size_t)(col0 + r) * ldb + k0 + kq * 4);
        }
    };

    const int T = K >> 5;
    stage(0, 0);
    cp_commit();

    for (int t = 0; t < T; ++t) {
        if (t + 1 < T) { stage((t + 1) & 1, (t + 1) << 5); cp_commit(); cp_wait1(); }
        else           { cp_wait0(); }
        __syncthreads();

        const uint32_t* As = sm + (t & 1) * STG;
        const uint32_t* Bs = As + ASTG;

#pragma unroll
        for (int ks = 0; ks < 32; ks += 8) {
            uint32_t a[2][4], b[NF][2];
#pragma unroll
            for (int mf = 0; mf < 2; mf++) {
                const int m0 = wm * 32 + mf * 16;
                a[mf][0] = As[(m0 + g) * 36 + ks + tg];
                a[mf][1] = As[(m0 + 8 + g) * 36 + ks + tg];
                a[mf][2] = As[(m0 + g) * 36 + ks + 4 + tg];
                a[mf][3] = As[(m0 + 8 + g) * 36 + ks + 4 + tg];
            }
#pragma unroll
            for (int nf = 0; nf < NF; nf++) {
                const int n0 = wn * NF * 8 + nf * 8;
                b[nf][0] = Bs[(n0 + g) * 36 + ks + tg];
                b[nf][1] = Bs[(n0 + g) * 36 + ks + 4 + tg];
            }
#pragma unroll
            for (int mf = 0; mf < 2; mf++)
#pragma unroll
                for (int nf = 0; nf < NF; nf++)
                    mma8(acc[mf][nf], a[mf], b[nf]);
        }
        __syncthreads();
    }

#pragma unroll
    for (int mf = 0; mf < 2; mf++) {
#pragma unroll
        for (int nf = 0; nf < NF; nf++) {
            const int r = row0 + wm * 32 + mf * 16 + g;
            const int c = col0 + wn * NF * 8 + nf * 8 + 2 * tg;
#pragma unroll
            for (int q = 0; q < 4; q++) {
                const int rr = r + (q >> 1) * 8;
                const int cc = c + (q & 1);
                float v = acc[mf][nf][q] * alpha;
                if (bias)  v += bias[cc];
                if (resid) v += resid[(size_t)rr * ldres + cc];
                if (relu)  v = fmaxf(v, 0.f);
                if (round_out) v = f2tf_f(v);
                C[(size_t)rr * ldc + cc] = v;
            }
        }
    }
}

// ============================================================================
// PV: O[b, l, h*256+e] = P[z] @ V[z]  (z = b*8+h). Inputs pre-rounded.
// Vs staged [k][n] pitch 136; 2-stage cp.async; output tf32-rounded.
// ============================================================================
__global__ __launch_bounds__(256, 2)
void av_tf32(const float* __restrict__ P, const float* __restrict__ Vb,
             float* __restrict__ O)
{
    constexpr int ASTG = 128 * 36;
    constexpr int VSTG = 32 * 136;
    constexpr int STG  = ASTG + VSTG;
    extern __shared__ uint32_t sm[];

    const int z = blockIdx.z, b = z >> 3, h = z & 7;
    const float* A = P + (size_t)z * L_ * L_;
    const float* V = Vb + (size_t)b * L_ * HD_ + h * D_;

    const int tid  = threadIdx.x;
    const int row0 = blockIdx.y * 128, col0 = blockIdx.x * 128;
    const int warp = tid >> 5, lane = tid & 31;
    const int wm = warp & 3, wn = warp >> 2;
    const int g = lane >> 2, tg = lane & 3;

    const uint32_t smb = (uint32_t)__cvta_generic_to_shared(sm);

    float acc[2][8][4] = {};

    auto stage = [&](int st, int k0) {
        const uint32_t baseA = smb + (uint32_t)(st * STG) * 4u;
        const uint32_t baseV = baseA + (uint32_t)ASTG * 4u;
#pragma unroll
        for (int i = 0; i < 4; i++) {
            const int s = tid + i * 256, r = s >> 3, kq = s & 7;
            cp16(baseA + (uint32_t)(r * 36 + kq * 4) * 4u,
                 A + (size_t)(row0 + r) * L_ + k0 + kq * 4);
        }
#pragma unroll
        for (int i = 0; i < 4; i++) {
            const int s = tid + i * 256, j = s >> 5, eg = s & 31;
            cp16(baseV + (uint32_t)(j * 136 + eg * 4) * 4u,
                 V + (size_t)(k0 + j) * HD_ + col0 + eg * 4);
        }
    };

    const int T = L_ >> 5;
    stage(0, 0);
    cp_commit();

    for (int t = 0; t < T; ++t) {
        if (t + 1 < T) { stage((t + 1) & 1, (t + 1) << 5); cp_commit(); cp_wait1(); }
        else           { cp_wait0(); }
        __syncthreads();

        const uint32_t* As = sm + (t & 1) * STG;
        const uint32_t* Vs = As + ASTG;

#pragma unroll
        for (int ks = 0; ks < 32; ks += 8) {
            uint32_t a[2][4], bfr[8][2];
#pragma unroll
            for (int mf = 0; mf < 2; mf++) {
                const int m0 = wm * 32 + mf * 16;
                a[mf][0] = As[(m0 + g) * 36 + ks + tg];
                a[mf][1] = As[(m0 + 8 + g) * 36 + ks + tg];
                a[mf][2] = As[(m0 + g) * 36 + ks + 4 + tg];
                a[mf][3] = As[(m0 + 8 + g) * 36 + ks + 4 + tg];
            }
#pragma unroll
            for (int nf = 0; nf < 8; nf++) {
                const int n0 = wn * 64 + nf * 8;
                bfr[nf][0] = Vs[(ks + tg) * 136 + n0 + g];
                bfr[nf][1] = Vs[(ks + 4 + tg) * 136 + n0 + g];
            }
#pragma unroll
            for (int mf = 0; mf < 2; mf++)
#pragma unroll
                for (int nf = 0; nf < 8; nf++)
                    mma8(acc[mf][nf], a[mf], bfr[nf]);
        }
        __syncthreads();
    }

#pragma unroll
    for (int mf = 0; mf < 2; mf++) {
#pragma unroll
        for (int nf = 0; nf < 8; nf++) {
            const int r = row0 + wm * 32 + mf * 16 + g;
            const int c = col0 + wn * 64 + nf * 8 + 2 * tg;
#pragma unroll
            for (int q = 0; q < 4; q++) {
                const int rr = r + (q >> 1) * 8;
                const int cc = c + (q & 1);
                O[(size_t)(b * L_ + rr) * HD_ + h * D_ + cc] = f2tf_f(acc[mf][nf][q]);
            }
        }
    }
}

// --------------------------- softmax (rounds probs to tf32) ------------------
__global__ void softmax_kernel(float* __restrict__ S)
{
    __shared__ float red[8];
    const size_t row = blockIdx.x;
    float* p = S + row * (size_t)L_;
    const int t = threadIdx.x;

    float4 v = reinterpret_cast<float4*>(p)[t];
    float m = fmaxf(fmaxf(v.x, v.y), fmaxf(v.z, v.w));
#pragma unroll
    for (int o = 16; o; o >>= 1) m = fmaxf(m, __shfl_xor_sync(~0u, m, o));
    if ((t & 31) == 0) red[t >> 5] = m;
    __syncthreads();
    float mm = red[0];
#pragma unroll
    for (int i = 1; i < 8; i++) mm = fmaxf(mm, red[i]);
    __syncthreads();

    v.x = expf(v.x - mm); v.y = expf(v.y - mm);
    v.z = expf(v.z - mm); v.w = expf(v.w - mm);
    float s = v.x + v.y + v.z + v.w;
#pragma unroll
    for (int o = 16; o; o >>= 1) s += __shfl_xor_sync(~0u, s, o);
    if ((t & 31) == 0) red[t >> 5] = s;
    __syncthreads();
    float ss = 0.f;
#pragma unroll
    for (int i = 0; i < 8; i++) ss += red[i];
    const float inv = 1.f / ss;
    v.x = f2tf_f(v.x * inv); v.y = f2tf_f(v.y * inv);
    v.z = f2tf_f(v.z * inv); v.w = f2tf_f(v.w * inv);
    reinterpret_cast<float4*>(p)[t] = v;
}

// --------------------------- layernorm (exact out + optional rounded) --------
__global__ void ln_kernel(const float* __restrict__ in, float* __restrict__ out,
                          float* __restrict__ out_r,
                          const float* __restrict__ g, const float* __restrict__ be)
{
    __shared__ float r1[8], r2[8];
    const int row = blockIdx.x, t = threadIdx.x;
    const float v = in[(size_t)row * D_ + t];
    float s = v, q = v * v;
#pragma unroll
    for (int o = 16; o; o >>= 1) {
        s += __shfl_xor_sync(~0u, s, o);
        q += __shfl_xor_sync(~0u, q, o);
    }
    if ((t & 31) == 0) { r1[t >> 5] = s; r2[t >> 5] = q; }
    __syncthreads();
    float S = 0.f, Q = 0.f;
#pragma unroll
    for (int i = 0; i < 8; i++) { S += r1[i]; Q += r2[i]; }
    const float mean = S * (1.f / D_);
    const float var = Q * (1.f / D_) - mean * mean;
    const float y = (v - mean) * rsqrtf(var + EPS_) * g[t] + be[t];
    out[(size_t)row * D_ + t] = y;
    if (out_r) out_r[(size_t)row * D_ + t] = f2tf_f(y);
}

// --------------------------- launch ------------------------------------------
extern "C" void kernel_launch(void* const* d_in, const int* in_sizes, int n_in,
                              void* d_out, int out_size)
{
    const float* x   = (const float*)d_in[0];
    const float* Wq  = (const float*)d_in[1];
    const float* Wk  = (const float*)d_in[2];
    const float* Wv  = (const float*)d_in[3];
    const float* Wu  = (const float*)d_in[4];
    const float* bu  = (const float*)d_in[5];
    const float* W1  = (const float*)d_in[6];
    const float* b1  = (const float*)d_in[7];
    const float* W2  = (const float*)d_in[8];
    const float* b2  = (const float*)d_in[9];
    const float* g1  = (const float*)d_in[10];
    const float* be1 = (const float*)d_in[11];
    const float* g2  = (const float*)d_in[12];
    const float* be2 = (const float*)d_in[13];
    float* out = (float*)d_out;

    float *Qb, *Kb, *Vb, *S, *O, *R1, *Z1, *Z1r, *Hb, *F;
    float *xr, *Wqr, *Wkr, *Wvr, *Wur, *W1r, *W2r;
    cudaGetSymbolAddress((void**)&Qb, g_Q);
    cudaGetSymbolAddress((void**)&Kb, g_K);
    cudaGetSymbolAddress((void**)&Vb, g_V);
    cudaGetSymbolAddress((void**)&S,  g_S);
    cudaGetSymbolAddress((void**)&O,  g_O);
    cudaGetSymbolAddress((void**)&R1, g_R1);
    cudaGetSymbolAddress((void**)&Z1, g_Z1);
    cudaGetSymbolAddress((void**)&Z1r, g_Z1r);
    cudaGetSymbolAddress((void**)&Hb, g_Hb);
    cudaGetSymbolAddress((void**)&F,  g_F);
    cudaGetSymbolAddress((void**)&xr,  g_xr);
    cudaGetSymbolAddress((void**)&Wqr, g_Wqr);
    cudaGetSymbolAddress((void**)&Wkr, g_Wkr);
    cudaGetSymbolAddress((void**)&Wvr, g_Wvr);
    cudaGetSymbolAddress((void**)&Wur, g_Wur);
    cudaGetSymbolAddress((void**)&W1r, g_W1r);
    cudaGetSymbolAddress((void**)&W2r, g_W2r);

    // opt-in dynamic smem (idempotent; not captured as graph nodes)
    constexpr int SMEM8  = 2 * (128 * 36 + 128 * 36) * 4;   // 73728
    constexpr int SMEM4  = 2 * (128 * 36 + 64 * 36) * 4;    // 55296
    constexpr int SMEMAV = 2 * (128 * 36 + 32 * 136) * 4;   // 71680
    cudaFuncSetAttribute(mm_tf32<8>, cudaFuncAttributeMaxDynamicSharedMemorySize, SMEM8);
    cudaFuncSetAttribute(mm_tf32<4>, cudaFuncAttributeMaxDynamicSharedMemorySize, SMEM4);
    cudaFuncSetAttribute(av_tf32,    cudaFuncAttributeMaxDynamicSharedMemorySize, SMEMAV);

    // round inputs to tf32 copies
    cvt_tf32_kernel<<<512, 256>>>((const float4*)x,  (float4*)xr,  ROWS_ * D_ / 4);
    cvt_tf32_kernel<<<256, 256>>>((const float4*)Wq, (float4*)Wqr, HD_ * D_ / 4);
    cvt_tf32_kernel<<<256, 256>>>((const float4*)Wk, (float4*)Wkr, HD_ * D_ / 4);
    cvt_tf32_kernel<<<256, 256>>>((const float4*)Wv, (float4*)Wvr, HD_ * D_ / 4);
    cvt_tf32_kernel<<<256, 256>>>((const float4*)Wu, (float4*)Wur, D_ * HD_ / 4);
    cvt_tf32_kernel<<<128, 256>>>((const float4*)W1, (float4*)W1r, F_ * D_ / 4);
    cvt_tf32_kernel<<<128, 256>>>((const float4*)W2, (float4*)W2r, D_ * F_ / 4);

    const long long LL2 = (long long)L_ * L_;

    // QKV projections (outputs tf32-rounded)
    mm_tf32<8><<<dim3(HD_ / 128, ROWS_ / 128, 1), 256, SMEM8>>>(xr, Wqr, Qb, D_, D_, D_, HD_,
        0, 0, 0, 0, 0, 0, 1.f, nullptr, nullptr, 0, 0, 1);
    mm_tf32<8><<<dim3(HD_ / 128, ROWS_ / 128, 1), 256, SMEM8>>>(xr, Wkr, Kb, D_, D_, D_, HD_,
        0, 0, 0, 0, 0, 0, 1.f, nullptr, nullptr, 0, 0, 1);
    mm_tf32<8><<<dim3(HD_ / 128, ROWS_ / 128, 1), 256, SMEM8>>>(xr, Wvr, Vb, D_, D_, D_, HD_,
        0, 0, 0, 0, 0, 0, 1.f, nullptr, nullptr, 0, 0, 1);

    // scores: per (b,h) Q @ K^T / 16
    mm_tf32<8><<<dim3(L_ / 128, L_ / 128, B_ * H_), 256, SMEM8>>>(Qb, Kb, S, D_, HD_, HD_, L_,
        (long long)L_ * HD_, D_, (long long)L_ * HD_, D_, 8 * LL2, LL2,
        0.0625f, nullptr, nullptr, 0, 0, 0);

    softmax_kernel<<<B_ * H_ * L_, 256>>>(S);

    av_tf32<<<dim3(D_ / 128, L_ / 128, B_ * H_), 256, SMEMAV>>>(S, Vb, O);

    // output projection + bias + residual(x)  [BN=64 -> 256 CTAs]
    mm_tf32<4><<<dim3(D_ / 64, ROWS_ / 128, 1), 256, SMEM4>>>(O, Wur, R1, HD_, HD_, HD_, D_,
        0, 0, 0, 0, 0, 0, 1.f, bu, x, D_, 0, 0);
    ln_kernel<<<ROWS_, 256>>>(R1, Z1, Z1r, g1, be1);

    // FFN
    mm_tf32<8><<<dim3(F_ / 128, ROWS_ / 128, 1), 256, SMEM8>>>(Z1r, W1r, Hb, D_, D_, D_, F_,
        0, 0, 0, 0, 0, 0, 1.f, b1, nullptr, 0, 1, 1);
    mm_tf32<4><<<dim3(D_ / 64, ROWS_ / 128, 1), 256, SMEM4>>>(Hb, W2r, F, F_, F_, F_, D_,
        0, 0, 0, 0, 0, 0, 1.f, b2, Z1, D_, 0, 0);
    ln_kernel<<<ROWS_, 256>>>(F, out, nullptr, g2, be2);
}